// round 1
// baseline (speedup 1.0000x reference)
#include <cuda_runtime.h>

#define HID 64
#define INCH 128

static const int MAXN = 100000;
static const int MAXE = 3200000;

// Scratch (allocation-free rule: __device__ globals)
__device__ float g_h[MAXN * HID];      // x @ W1
__device__ float g_out1[MAXN * HID];   // layer-1 aggregated output
__device__ float g_dinv[MAXN];         // deg accumulator, then rsqrt(deg)
__device__ float g_norm[MAXE];         // dinv[row]*ew*dinv[col]
__device__ float g_z[MAXN];            // relu(out1+b1) @ W2

__device__ __forceinline__ void red_add_v4(float* addr, float4 v) {
    asm volatile("red.global.add.v4.f32 [%0], {%1,%2,%3,%4};"
                 :: "l"(addr), "f"(v.x), "f"(v.y), "f"(v.z), "f"(v.w)
                 : "memory");
}

// ---------------- degree / dinv ----------------
__global__ void k_deg_init(int n) {
    int i = blockIdx.x * blockDim.x + threadIdx.x;
    if (i < n) g_dinv[i] = 1.0f;   // self-loop weight
}

__global__ void k_deg_acc(const int* __restrict__ col, const float* __restrict__ ew, int e) {
    int i = blockIdx.x * blockDim.x + threadIdx.x;
    if (i < e) atomicAdd(&g_dinv[col[i]], ew[i]);
}

__global__ void k_deg_fin(int n) {
    int i = blockIdx.x * blockDim.x + threadIdx.x;
    if (i < n) {
        float d = g_dinv[i];
        g_dinv[i] = (d > 0.0f) ? rsqrtf(d) : 0.0f;
    }
}

// ---------------- h = x @ W1 ----------------
// 16 rows per 256-thread block. W1 (128x64) and the x tile staged in smem.
__global__ void k_gemm1(const float* __restrict__ x, const float* __restrict__ W1, int n) {
    __shared__ float sx[16 * INCH];      // 8 KB
    __shared__ float sw[INCH * HID];     // 32 KB
    int base = blockIdx.x * 16;

    for (int i = threadIdx.x; i < INCH * HID; i += 256) sw[i] = W1[i];
    int rows = n - base; if (rows > 16) rows = 16;
    for (int i = threadIdx.x; i < rows * INCH; i += 256) sx[i] = x[base * INCH + i];
    __syncthreads();

    int c  = threadIdx.x & 63;
    int r0 = threadIdx.x >> 6;           // 0..3; handles rows r0, r0+4, r0+8, r0+12
    float a0 = 0.f, a1 = 0.f, a2 = 0.f, a3 = 0.f;
#pragma unroll 8
    for (int k = 0; k < INCH; k++) {
        float w = sw[k * HID + c];
        a0 += sx[(r0     ) * INCH + k] * w;
        a1 += sx[(r0 +  4) * INCH + k] * w;
        a2 += sx[(r0 +  8) * INCH + k] * w;
        a3 += sx[(r0 + 12) * INCH + k] * w;
    }
    if (base + r0      < n) g_h[(base + r0     ) * HID + c] = a0;
    if (base + r0 + 4  < n) g_h[(base + r0 +  4) * HID + c] = a1;
    if (base + r0 + 8  < n) g_h[(base + r0 +  8) * HID + c] = a2;
    if (base + r0 + 12 < n) g_h[(base + r0 + 12) * HID + c] = a3;
}

// ---------------- edge norms ----------------
__global__ void k_norm(const int* __restrict__ row, const int* __restrict__ col,
                       const float* __restrict__ ew, int e) {
    int i = blockIdx.x * blockDim.x + threadIdx.x;
    if (i < e) g_norm[i] = g_dinv[row[i]] * ew[i] * g_dinv[col[i]];
}

// ---------------- out1 init = self-loop term ----------------
__global__ void k_init_out1(int n) {
    int idx = blockIdx.x * blockDim.x + threadIdx.x;   // n*16 float4 slots
    if (idx >= n * 16) return;
    int i = idx >> 4;
    float d = g_dinv[i];
    float s = d * d;
    float4 v = reinterpret_cast<const float4*>(g_h)[idx];
    v.x *= s; v.y *= s; v.z *= s; v.w *= s;
    reinterpret_cast<float4*>(g_out1)[idx] = v;
}

// ---------------- layer-1 scatter: 16 threads per edge, float4 RED ----------------
__global__ void k_scatter1(const int* __restrict__ row, const int* __restrict__ col, int e) {
    int tid = blockIdx.x * blockDim.x + threadIdx.x;   // e*16 = 51.2M fits int
    if (tid >= e * 16) return;
    int ei = tid >> 4;
    int g  = tid & 15;
    float nrm = g_norm[ei];
    int r = row[ei];
    int c = col[ei];
    float4 v = reinterpret_cast<const float4*>(g_h)[r * 16 + g];
    v.x *= nrm; v.y *= nrm; v.z *= nrm; v.w *= nrm;
    red_add_v4(&g_out1[c * HID + g * 4], v);
}

// ---------------- relu + bias + z = h2 @ W2 (warp per node) ----------------
__global__ void k_relu_z(const float* __restrict__ b1, const float* __restrict__ W2, int n) {
    int gtid = blockIdx.x * blockDim.x + threadIdx.x;
    int wid  = gtid >> 5;
    int lane = threadIdx.x & 31;
    if (wid >= n) return;
    float a = g_out1[wid * HID + lane]      + b1[lane];
    float b = g_out1[wid * HID + 32 + lane] + b1[32 + lane];
    a = fmaxf(a, 0.f);
    b = fmaxf(b, 0.f);
    float s = a * W2[lane] + b * W2[32 + lane];
#pragma unroll
    for (int o = 16; o; o >>= 1) s += __shfl_down_sync(0xffffffffu, s, o);
    if (lane == 0) g_z[wid] = s;
}

// ---------------- output init = self-loop term + bias ----------------
__global__ void k_out_init(float* __restrict__ out, const float* __restrict__ b2, int n) {
    int i = blockIdx.x * blockDim.x + threadIdx.x;
    if (i < n) {
        float d = g_dinv[i];
        out[i] = g_z[i] * d * d + b2[0];
    }
}

// ---------------- layer-2 scatter (scalar) ----------------
__global__ void k_scatter2(const int* __restrict__ row, const int* __restrict__ col,
                           float* __restrict__ out, int e) {
    int i = blockIdx.x * blockDim.x + threadIdx.x;
    if (i < e) atomicAdd(&out[col[i]], g_z[row[i]] * g_norm[i]);
}

extern "C" void kernel_launch(void* const* d_in, const int* in_sizes, int n_in,
                              void* d_out, int out_size) {
    const float* x   = (const float*)d_in[0];
    const int*   ei  = (const int*)  d_in[1];   // [2, E] row-major
    const float* ea  = (const float*)d_in[2];   // [E, 1]
    const float* W1  = (const float*)d_in[3];
    const float* b1  = (const float*)d_in[4];
    const float* W2  = (const float*)d_in[5];
    const float* b2  = (const float*)d_in[6];
    float* out = (float*)d_out;

    int n = in_sizes[0] / INCH;
    int e = in_sizes[2];
    const int* row = ei;
    const int* col = ei + e;

    const int T = 256;
    auto cdiv = [](int a, int b) { return (a + b - 1) / b; };

    // degree / dinv
    k_deg_init<<<cdiv(n, T), T>>>(n);
    k_deg_acc <<<cdiv(e, T), T>>>(col, ea, e);
    k_deg_fin <<<cdiv(n, T), T>>>(n);

    // h = x @ W1 (independent of deg; serialized on default stream, fine)
    k_gemm1<<<cdiv(n, 16), T>>>(x, W1, n);

    // per-edge norms
    k_norm<<<cdiv(e, T), T>>>(row, col, ea, e);

    // layer 1 aggregation
    k_init_out1<<<cdiv(n * 16, T), T>>>(n);
    k_scatter1 <<<cdiv(e * 16, T), T>>>(row, col, e);

    // relu + bias + @W2
    k_relu_z<<<cdiv(n * 32, T), T>>>(b1, W2, n);

    // layer 2 aggregation (scalar)
    k_out_init<<<cdiv(n, T), T>>>(out, b2, n);
    k_scatter2<<<cdiv(e, T), T>>>(row, col, out, e);
}

// round 2
// speedup vs baseline: 1.1682x; 1.1682x over previous
#include <cuda_runtime.h>

#define HID 64
#define INCH 128

static const int MAXN = 100000;
static const int MAXE = 3200000;

// Scratch (allocation-free rule: __device__ globals)
__device__ float g_h[MAXN * HID];      // x @ W1
__device__ float g_out1[MAXN * HID];   // layer-1 aggregated output
__device__ float g_dinv[MAXN];         // deg accumulator, then rsqrt(deg)
__device__ float g_norm[MAXE];         // dinv[row]*ew*dinv[col]
__device__ float g_z[MAXN];            // relu(out1+b1) @ W2

__device__ __forceinline__ void red_add_v4(float* addr, float4 v) {
    asm volatile("red.global.add.v4.f32 [%0], {%1,%2,%3,%4};"
                 :: "l"(addr), "f"(v.x), "f"(v.y), "f"(v.z), "f"(v.w)
                 : "memory");
}

// ---------------- degree / dinv ----------------
__global__ void k_deg_init(int n) {
    int i = blockIdx.x * blockDim.x + threadIdx.x;
    if (i < n) g_dinv[i] = 1.0f;   // self-loop weight
}

__global__ void k_deg_acc(const int* __restrict__ col, const float* __restrict__ ew, int e) {
    int i = blockIdx.x * blockDim.x + threadIdx.x;
    if (i < e) atomicAdd(&g_dinv[col[i]], ew[i]);
}

__global__ void k_deg_fin(int n) {
    int i = blockIdx.x * blockDim.x + threadIdx.x;
    if (i < n) {
        float d = g_dinv[i];
        g_dinv[i] = (d > 0.0f) ? rsqrtf(d) : 0.0f;
    }
}

// ---------------- h = x @ W1, fused self-loop epilogue ----------------
// Register-tiled GEMM: BM=128 rows, BN=64 cols (full HID), BK=8.
// 256 threads; each computes an 8x4 register tile.
// Epilogue writes g_h AND g_out1 = h * dinv^2 (self-loop term).
__global__ __launch_bounds__(256) void k_gemm1(const float* __restrict__ x,
                                               const float* __restrict__ W1, int n) {
    __shared__ float sx[8][128 + 4];   // [kk][row], padded
    __shared__ float sw[8][HID];       // [kk][col]

    const int base = blockIdx.x * 128;
    const int tid  = threadIdx.x;
    const int tx   = tid & 15;         // col group: cols tx*4 .. tx*4+3
    const int ty   = tid >> 4;         // row group: rows ty*8 .. ty*8+7

    // x-tile load mapping: thread loads one float4 of x per K-step
    const int lrow = tid >> 1;         // 0..127
    const int lh   = (tid & 1) * 4;    // kk offset 0 or 4

    float acc[8][4];
#pragma unroll
    for (int i = 0; i < 8; i++)
#pragma unroll
        for (int j = 0; j < 4; j++) acc[i][j] = 0.0f;

    for (int k0 = 0; k0 < INCH; k0 += 8) {
        // load x tile (transpose to k-major in smem)
        float4 xv = make_float4(0.f, 0.f, 0.f, 0.f);
        if (base + lrow < n)
            xv = *reinterpret_cast<const float4*>(&x[(base + lrow) * INCH + k0 + lh]);
        sx[lh + 0][lrow] = xv.x;
        sx[lh + 1][lrow] = xv.y;
        sx[lh + 2][lrow] = xv.z;
        sx[lh + 3][lrow] = xv.w;
        // load W1 tile: 8x64 = 512 floats, 2 per thread
        reinterpret_cast<float*>(sw)[tid]       = W1[(k0 * HID) + tid];
        reinterpret_cast<float*>(sw)[tid + 256] = W1[(k0 * HID) + tid + 256];
        __syncthreads();

#pragma unroll
        for (int kk = 0; kk < 8; kk++) {
            float4 b = *reinterpret_cast<const float4*>(&sw[kk][tx * 4]);
            float4 a0 = *reinterpret_cast<const float4*>(&sx[kk][ty * 8]);
            float4 a1 = *reinterpret_cast<const float4*>(&sx[kk][ty * 8 + 4]);
            float a[8] = {a0.x, a0.y, a0.z, a0.w, a1.x, a1.y, a1.z, a1.w};
#pragma unroll
            for (int i = 0; i < 8; i++) {
                acc[i][0] += a[i] * b.x;
                acc[i][1] += a[i] * b.y;
                acc[i][2] += a[i] * b.z;
                acc[i][3] += a[i] * b.w;
            }
        }
        __syncthreads();
    }

    // epilogue: write h and out1 = h * dinv^2 (self-loop contribution)
#pragma unroll
    for (int i = 0; i < 8; i++) {
        int r = base + ty * 8 + i;
        if (r < n) {
            float d = g_dinv[r];
            float s = d * d;
            float4 v = make_float4(acc[i][0], acc[i][1], acc[i][2], acc[i][3]);
            *reinterpret_cast<float4*>(&g_h[r * HID + tx * 4]) = v;
            float4 vs = make_float4(v.x * s, v.y * s, v.z * s, v.w * s);
            *reinterpret_cast<float4*>(&g_out1[r * HID + tx * 4]) = vs;
        }
    }
}

// ---------------- edge norms ----------------
__global__ void k_norm(const int* __restrict__ row, const int* __restrict__ col,
                       const float* __restrict__ ew, int e) {
    int i = blockIdx.x * blockDim.x + threadIdx.x;
    if (i < e) g_norm[i] = g_dinv[row[i]] * ew[i] * g_dinv[col[i]];
}

// ---------------- layer-1 scatter: 16 threads per edge, float4 RED ----------------
__global__ void k_scatter1(const int* __restrict__ row, const int* __restrict__ col, int e) {
    int tid = blockIdx.x * blockDim.x + threadIdx.x;   // e*16 = 51.2M fits int
    if (tid >= e * 16) return;
    int ei = tid >> 4;
    int g  = tid & 15;
    float nrm = g_norm[ei];
    int r = row[ei];
    int c = col[ei];
    float4 v = reinterpret_cast<const float4*>(g_h)[r * 16 + g];
    v.x *= nrm; v.y *= nrm; v.z *= nrm; v.w *= nrm;
    red_add_v4(&g_out1[c * HID + g * 4], v);
}

// ---------------- relu + bias + z = h2 @ W2 (warp per node) ----------------
__global__ void k_relu_z(const float* __restrict__ b1, const float* __restrict__ W2, int n) {
    int gtid = blockIdx.x * blockDim.x + threadIdx.x;
    int wid  = gtid >> 5;
    int lane = threadIdx.x & 31;
    if (wid >= n) return;
    float a = g_out1[wid * HID + lane]      + b1[lane];
    float b = g_out1[wid * HID + 32 + lane] + b1[32 + lane];
    a = fmaxf(a, 0.f);
    b = fmaxf(b, 0.f);
    float s = a * W2[lane] + b * W2[32 + lane];
#pragma unroll
    for (int o = 16; o; o >>= 1) s += __shfl_down_sync(0xffffffffu, s, o);
    if (lane == 0) g_z[wid] = s;
}

// ---------------- output init = self-loop term + bias ----------------
__global__ void k_out_init(float* __restrict__ out, const float* __restrict__ b2, int n) {
    int i = blockIdx.x * blockDim.x + threadIdx.x;
    if (i < n) {
        float d = g_dinv[i];
        out[i] = g_z[i] * d * d + b2[0];
    }
}

// ---------------- layer-2 scatter (scalar) ----------------
__global__ void k_scatter2(const int* __restrict__ row, const int* __restrict__ col,
                           float* __restrict__ out, int e) {
    int i = blockIdx.x * blockDim.x + threadIdx.x;
    if (i < e) atomicAdd(&out[col[i]], g_z[row[i]] * g_norm[i]);
}

extern "C" void kernel_launch(void* const* d_in, const int* in_sizes, int n_in,
                              void* d_out, int out_size) {
    const float* x   = (const float*)d_in[0];
    const int*   ei  = (const int*)  d_in[1];   // [2, E] row-major
    const float* ea  = (const float*)d_in[2];   // [E, 1]
    const float* b1  = (const float*)d_in[4];
    const float* W2  = (const float*)d_in[5];
    const float* b2  = (const float*)d_in[6];
    const float* W1  = (const float*)d_in[3];
    float* out = (float*)d_out;

    int n = in_sizes[0] / INCH;
    int e = in_sizes[2];
    const int* row = ei;
    const int* col = ei + e;

    const int T = 256;
    auto cdiv = [](int a, int b) { return (a + b - 1) / b; };

    // degree / dinv (must precede gemm epilogue which uses dinv)
    k_deg_init<<<cdiv(n, T), T>>>(n);
    k_deg_acc <<<cdiv(e, T), T>>>(col, ea, e);
    k_deg_fin <<<cdiv(n, T), T>>>(n);

    // h = x @ W1, fused with self-loop init of out1
    k_gemm1<<<cdiv(n, 128), T>>>(x, W1, n);

    // per-edge norms
    k_norm<<<cdiv(e, T), T>>>(row, col, ea, e);

    // layer 1 aggregation (atomic scatter)
    k_scatter1<<<cdiv(e * 16, T), T>>>(row, col, e);

    // relu + bias + @W2
    k_relu_z<<<cdiv(n * 32, T), T>>>(b1, W2, n);

    // layer 2 aggregation (scalar)
    k_out_init<<<cdiv(n, T), T>>>(out, b2, n);
    k_scatter2<<<cdiv(e, T), T>>>(row, col, out, e);
}

// round 3
// speedup vs baseline: 1.5627x; 1.3377x over previous
#include <cuda_runtime.h>

#define HID 64
#define INCH 128

static const int MAXN = 100000;
static const int MAXE = 3200000;

// Scratch (allocation-free rule: __device__ globals)
__device__ float g_h[MAXN * HID];        // x @ W1
__device__ float g_dinv[MAXN];           // deg accumulator -> rsqrt(deg)
__device__ int   g_cnt[MAXN];            // in-degree histogram (edge count)
__device__ int   g_start[MAXN + 1];      // CSR offsets by destination
__device__ int   g_pos[MAXN];            // fill cursors
__device__ int   g_bsum[128];            // scan partials
__device__ int2  g_edge[MAXE];           // packed {row, norm as float bits}, dest-sorted
__device__ float g_z[MAXN];              // relu(agg1+b1) @ W2

// ---------------- init: deg=1 (self loop), cnt=0 ----------------
__global__ void k_init(int n) {
    int i = blockIdx.x * blockDim.x + threadIdx.x;
    if (i < n) { g_dinv[i] = 1.0f; g_cnt[i] = 0; }
}

// ---------------- histogram + weighted degree ----------------
__global__ void k_hist(const int* __restrict__ col, const float* __restrict__ ew, int e) {
    int i = blockIdx.x * blockDim.x + threadIdx.x;
    if (i < e) {
        int c = col[i];
        atomicAdd(&g_dinv[c], ew[i]);
        atomicAdd(&g_cnt[c], 1);
    }
}

__global__ void k_deg_fin(int n) {
    int i = blockIdx.x * blockDim.x + threadIdx.x;
    if (i < n) {
        float d = g_dinv[i];
        g_dinv[i] = (d > 0.0f) ? rsqrtf(d) : 0.0f;
    }
}

// ---------------- exclusive scan of g_cnt -> g_start ----------------
__global__ __launch_bounds__(1024) void k_scan1(int n) {
    __shared__ int sh[1024];
    int i = blockIdx.x * 1024 + threadIdx.x;
    int v = (i < n) ? g_cnt[i] : 0;
    sh[threadIdx.x] = v;
    __syncthreads();
#pragma unroll
    for (int o = 1; o < 1024; o <<= 1) {
        int t = (threadIdx.x >= o) ? sh[threadIdx.x - o] : 0;
        __syncthreads();
        sh[threadIdx.x] += t;
        __syncthreads();
    }
    int incl = sh[threadIdx.x];
    if (i < n) g_start[i] = incl - v;                 // exclusive
    if (threadIdx.x == 1023) g_bsum[blockIdx.x] = incl;
}

__global__ void k_scan2(int nb) {
    if (threadIdx.x == 0 && blockIdx.x == 0) {
        int run = 0;
        for (int b = 0; b < nb; b++) { int t = g_bsum[b]; g_bsum[b] = run; run += t; }
    }
}

__global__ void k_scan3(int n, int e) {
    int i = blockIdx.x * blockDim.x + threadIdx.x;
    if (i < n) {
        int s = g_start[i] + g_bsum[i >> 10];
        g_start[i] = s;
        g_pos[i]   = s;
    } else if (i == n) {
        g_start[n] = e;
    }
}

// ---------------- CSR fill: dest-sorted {row, norm} records ----------------
__global__ void k_fill(const int* __restrict__ row, const int* __restrict__ col,
                       const float* __restrict__ ew, int e) {
    int i = blockIdx.x * blockDim.x + threadIdx.x;
    if (i < e) {
        int c = col[i];
        int r = row[i];
        float nrm = g_dinv[r] * ew[i] * g_dinv[c];
        int p = atomicAdd(&g_pos[c], 1);
        g_edge[p] = make_int2(r, __float_as_int(nrm));
    }
}

// ---------------- h = x @ W1 (register-tiled) ----------------
__global__ __launch_bounds__(256) void k_gemm1(const float* __restrict__ x,
                                               const float* __restrict__ W1, int n) {
    __shared__ float sx[8][128 + 4];
    __shared__ float sw[8][HID];

    const int base = blockIdx.x * 128;
    const int tid  = threadIdx.x;
    const int tx   = tid & 15;
    const int ty   = tid >> 4;
    const int lrow = tid >> 1;
    const int lh   = (tid & 1) * 4;

    float acc[8][4];
#pragma unroll
    for (int i = 0; i < 8; i++)
#pragma unroll
        for (int j = 0; j < 4; j++) acc[i][j] = 0.0f;

    for (int k0 = 0; k0 < INCH; k0 += 8) {
        float4 xv = make_float4(0.f, 0.f, 0.f, 0.f);
        if (base + lrow < n)
            xv = *reinterpret_cast<const float4*>(&x[(base + lrow) * INCH + k0 + lh]);
        sx[lh + 0][lrow] = xv.x;
        sx[lh + 1][lrow] = xv.y;
        sx[lh + 2][lrow] = xv.z;
        sx[lh + 3][lrow] = xv.w;
        reinterpret_cast<float*>(sw)[tid]       = W1[(k0 * HID) + tid];
        reinterpret_cast<float*>(sw)[tid + 256] = W1[(k0 * HID) + tid + 256];
        __syncthreads();

#pragma unroll
        for (int kk = 0; kk < 8; kk++) {
            float4 b  = *reinterpret_cast<const float4*>(&sw[kk][tx * 4]);
            float4 a0 = *reinterpret_cast<const float4*>(&sx[kk][ty * 8]);
            float4 a1 = *reinterpret_cast<const float4*>(&sx[kk][ty * 8 + 4]);
            float a[8] = {a0.x, a0.y, a0.z, a0.w, a1.x, a1.y, a1.z, a1.w};
#pragma unroll
            for (int i = 0; i < 8; i++) {
                acc[i][0] += a[i] * b.x;
                acc[i][1] += a[i] * b.y;
                acc[i][2] += a[i] * b.z;
                acc[i][3] += a[i] * b.w;
            }
        }
        __syncthreads();
    }

#pragma unroll
    for (int i = 0; i < 8; i++) {
        int r = base + ty * 8 + i;
        if (r < n)
            *reinterpret_cast<float4*>(&g_h[r * HID + tx * 4]) =
                make_float4(acc[i][0], acc[i][1], acc[i][2], acc[i][3]);
    }
}

// ---------------- layer-1 aggregate + relu + bias + @W2 (fused) ----------------
// One warp per destination node; lane owns h-columns lane and lane+32.
__global__ void k_agg1(const float* __restrict__ b1, const float* __restrict__ W2, int n) {
    int gtid = blockIdx.x * blockDim.x + threadIdx.x;
    int wid  = gtid >> 5;
    int lane = threadIdx.x & 31;
    if (wid >= n) return;

    int s  = g_start[wid];
    int en = g_start[wid + 1];
    float d  = g_dinv[wid];
    float sl = d * d;
    float a0 = g_h[wid * HID + lane]      * sl;    // self-loop term
    float a1 = g_h[wid * HID + 32 + lane] * sl;

    for (int p = s; p < en; p++) {
        int2 rec = g_edge[p];                       // broadcast load
        float nrm = __int_as_float(rec.y);
        const float* hr = &g_h[rec.x * HID];
        a0 += hr[lane]      * nrm;                  // coalesced 128B
        a1 += hr[32 + lane] * nrm;                  // coalesced 128B
    }

    a0 = fmaxf(a0 + b1[lane],      0.f) * W2[lane];
    a1 = fmaxf(a1 + b1[32 + lane], 0.f) * W2[32 + lane];
    float sum = a0 + a1;
#pragma unroll
    for (int o = 16; o; o >>= 1) sum += __shfl_down_sync(0xffffffffu, sum, o);
    if (lane == 0) g_z[wid] = sum;
}

// ---------------- layer-2 aggregate (gather, no atomics) ----------------
__global__ void k_agg2(float* __restrict__ out, const float* __restrict__ b2, int n) {
    int gtid = blockIdx.x * blockDim.x + threadIdx.x;
    int wid  = gtid >> 5;
    int lane = threadIdx.x & 31;
    if (wid >= n) return;

    int s  = g_start[wid];
    int en = g_start[wid + 1];
    float acc = 0.f;
    for (int p = s + lane; p < en; p += 32) {
        int2 rec = g_edge[p];                       // coalesced 8B stream
        acc += g_z[rec.x] * __int_as_float(rec.y);  // scalar gather
    }
#pragma unroll
    for (int o = 16; o; o >>= 1) acc += __shfl_down_sync(0xffffffffu, acc, o);
    if (lane == 0) {
        float d = g_dinv[wid];
        out[wid] = acc + g_z[wid] * d * d + b2[0];
    }
}

extern "C" void kernel_launch(void* const* d_in, const int* in_sizes, int n_in,
                              void* d_out, int out_size) {
    const float* x   = (const float*)d_in[0];
    const int*   ei  = (const int*)  d_in[1];   // [2, E] row-major
    const float* ea  = (const float*)d_in[2];   // [E, 1]
    const float* W1  = (const float*)d_in[3];
    const float* b1  = (const float*)d_in[4];
    const float* W2  = (const float*)d_in[5];
    const float* b2  = (const float*)d_in[6];
    float* out = (float*)d_out;

    int n = in_sizes[0] / INCH;
    int e = in_sizes[2];
    const int* row = ei;
    const int* col = ei + e;

    const int T = 256;
    auto cdiv = [](int a, int b) { return (a + b - 1) / b; };
    int nb = cdiv(n, 1024);

    k_init   <<<cdiv(n, T), T>>>(n);
    k_hist   <<<cdiv(e, T), T>>>(col, ea, e);
    k_deg_fin<<<cdiv(n, T), T>>>(n);

    k_scan1<<<nb, 1024>>>(n);
    k_scan2<<<1, 32>>>(nb);
    k_scan3<<<cdiv(n + 1, T), T>>>(n, e);

    k_gemm1<<<cdiv(n, 128), T>>>(x, W1, n);
    k_fill <<<cdiv(e, T), T>>>(row, col, ea, e);

    k_agg1<<<cdiv(n * 32, T), T>>>(b1, W2, n);
    k_agg2<<<cdiv(n * 32, T), T>>>(out, b2, n);
}